// round 11
// baseline (speedup 1.0000x reference)
#include <cuda_runtime.h>
#include <cuda_bf16.h>
#include <math.h>
#include <float.h>
#include <stdint.h>

// Problem constants
#define LSEQ   2048
#define DMODEL 1024
#define NHEAD  16
#define HSZ    64
#define BATCH  4
#define MTOT   (BATCH*LSEQ)      // 8192
#define KDIM   1024

// ---------------------------------------------------------------------------
// Scratch (device globals: allocation-free rule)
// ---------------------------------------------------------------------------
__device__ __nv_bfloat16 g_xhi[(size_t)MTOT * KDIM];
__device__ __nv_bfloat16 g_xlo[(size_t)MTOT * KDIM];
__device__ __nv_bfloat16 g_wthi[(size_t)3 * DMODEL * KDIM];
__device__ __nv_bfloat16 g_wtlo[(size_t)3 * DMODEL * KDIM];
__device__ __nv_bfloat16 g_qkvhi[(size_t)MTOT * 3 * DMODEL];
__device__ __nv_bfloat16 g_qkvlo[(size_t)MTOT * 3 * DMODEL];
__device__ __nv_bfloat16 g_erhi[(size_t)LSEQ * HSZ];
__device__ __nv_bfloat16 g_erlo[(size_t)LSEQ * HSZ];
__device__ __nv_bfloat16 g_yhi[(size_t)MTOT * DMODEL];
__device__ __nv_bfloat16 g_ylo[(size_t)MTOT * DMODEL];

// ---------------------------------------------------------------------------
// Helpers (compute_103-safe: mma.sync / ldmatrix / cp.async only)
// ---------------------------------------------------------------------------
__device__ __forceinline__ uint32_t smem_u32(const void* p) {
    uint32_t a;
    asm("{ .reg .u64 t; cvta.to.shared.u64 t, %1; cvt.u32.u64 %0, t; }"
        : "=r"(a) : "l"(p));
    return a;
}

#define CP_ASYNC16(dst, src) \
    asm volatile("cp.async.cg.shared.global [%0], [%1], 16;" :: "r"(dst), "l"(src))
#define CP_COMMIT() asm volatile("cp.async.commit_group;" ::: "memory")
#define CP_WAIT(n)  asm volatile("cp.async.wait_group %0;" :: "n"(n) : "memory")

__device__ __forceinline__ void cp16z(uint32_t dst, const void* src, bool ok) {
    int sz = ok ? 16 : 0;
    asm volatile("cp.async.cg.shared.global [%0], [%1], 16, %2;"
                 :: "r"(dst), "l"(src), "r"(sz));
}

__device__ __forceinline__ void ldsm4(uint32_t* r, uint32_t addr) {
    asm volatile("ldmatrix.sync.aligned.m8n8.x4.shared.b16 {%0,%1,%2,%3}, [%4];"
                 : "=r"(r[0]), "=r"(r[1]), "=r"(r[2]), "=r"(r[3]) : "r"(addr));
}

__device__ __forceinline__ void ldsm4t(uint32_t* r, uint32_t addr) {
    asm volatile("ldmatrix.sync.aligned.m8n8.x4.trans.shared.b16 {%0,%1,%2,%3}, [%4];"
                 : "=r"(r[0]), "=r"(r[1]), "=r"(r[2]), "=r"(r[3]) : "r"(addr));
}

__device__ __forceinline__ void mma16816(float* c, const uint32_t* a, const uint32_t* b) {
    asm volatile(
        "mma.sync.aligned.m16n8k16.row.col.f32.bf16.bf16.f32 "
        "{%0,%1,%2,%3}, {%4,%5,%6,%7}, {%8,%9}, {%0,%1,%2,%3};"
        : "+f"(c[0]), "+f"(c[1]), "+f"(c[2]), "+f"(c[3])
        : "r"(a[0]), "r"(a[1]), "r"(a[2]), "r"(a[3]), "r"(b[0]), "r"(b[1]));
}

__device__ __forceinline__ float ex2(float x) {
    float y;
    asm("ex2.approx.f32 %0, %1;" : "=f"(y) : "f"(x));
    return y;
}

__device__ __forceinline__ void split2(float v, unsigned short& h, unsigned short& l) {
    __nv_bfloat16 hb = __float2bfloat16(v);
    __nv_bfloat16 lb = __float2bfloat16(v - __bfloat162float(hb));
    h = __bfloat16_as_ushort(hb);
    l = __bfloat16_as_ushort(lb);
}

// ---------------------------------------------------------------------------
// Split fp32 -> bf16 (hi, lo).  n divisible by 1024.
// ---------------------------------------------------------------------------
__global__ __launch_bounds__(256) void split_bf16_kernel(
    const float* __restrict__ src, __nv_bfloat16* __restrict__ hi,
    __nv_bfloat16* __restrict__ lo, int n)
{
    int i = (blockIdx.x * 256 + threadIdx.x) * 4;
    if (i >= n) return;
    float4 v = *(const float4*)(src + i);
    ushort4 hv, lv;
    split2(v.x, hv.x, lv.x);
    split2(v.y, hv.y, lv.y);
    split2(v.z, hv.z, lv.z);
    split2(v.w, hv.w, lv.w);
    *(ushort4*)(hi + i) = hv;
    *(ushort4*)(lo + i) = lv;
}

// ---------------------------------------------------------------------------
// Transpose + split: W[K][N] fp32 -> Wt_hi[N][K], Wt_lo[N][K] bf16.
// ---------------------------------------------------------------------------
__global__ __launch_bounds__(256) void transpose_split_kernel(
    const float* __restrict__ W, __nv_bfloat16* __restrict__ Thi,
    __nv_bfloat16* __restrict__ Tlo, int K, int N)
{
    __shared__ float t[32][33];
    const int tx = threadIdx.x, ty = threadIdx.y;
    const int n0 = blockIdx.x * 32, k0 = blockIdx.y * 32;
    #pragma unroll
    for (int i = 0; i < 4; i++)
        t[ty + i * 8][tx] = W[(size_t)(k0 + ty + i * 8) * N + n0 + tx];
    __syncthreads();
    #pragma unroll
    for (int i = 0; i < 4; i++) {
        float v = t[tx][ty + i * 8];
        unsigned short h, l;
        split2(v, h, l);
        size_t o = (size_t)(n0 + ty + i * 8) * K + k0 + tx;
        Thi[o] = __ushort_as_bfloat16(h);
        Tlo[o] = __ushort_as_bfloat16(l);
    }
}

// ---------------------------------------------------------------------------
// HMMA bf16-split GEMM (unchanged from R10 measured-good version).
// ---------------------------------------------------------------------------
#define GM_NCH 32
#define GM_ROWB 80
#define GM_ARR (128 * GM_ROWB)
#define GM_STAGE (4 * GM_ARR)
#define GM_SMEM (2 * GM_STAGE)

__global__ __launch_bounds__(256, 2) void gemm_mma_kernel(
    const __nv_bfloat16* __restrict__ Ahi, const __nv_bfloat16* __restrict__ Alo,
    const __nv_bfloat16* __restrict__ Bhi, const __nv_bfloat16* __restrict__ Blo,
    const float* __restrict__ bias, float* __restrict__ C, int Ntot,
    __nv_bfloat16* __restrict__ Chi, __nv_bfloat16* __restrict__ Clo, int bf16out)
{
    extern __shared__ char smem[];
    const uint32_t sb = smem_u32(smem);
    const int tid = threadIdx.x;
    const int wid = tid >> 5;
    const int lane = tid & 31;
    const int warp_m = wid >> 2;
    const int warp_n = wid & 3;
    const int row0 = blockIdx.y * 128;
    const int col0 = blockIdx.x * 128;

    float acc[16][4];
    #pragma unroll
    for (int i = 0; i < 16; i++)
        #pragma unroll
        for (int j = 0; j < 4; j++) acc[i][j] = 0.f;

    const int arow = warp_m * 64 + (lane & 15);
    const int acb  = (lane >> 4);
    const int brow = warp_n * 32 + ((lane >> 4) & 1) * 8 + (lane & 7);
    const int bcb  = ((lane >> 3) & 1);

    auto prefetch = [&](int stage, int c) {
        const int k0 = c * 32;
        #pragma unroll
        for (int i = 0; i < 8; i++) {
            const int arr = i >> 1;
            const int rem = ((i & 1) << 8) + tid;
            const int r = rem >> 2;
            const int cb = rem & 3;
            const uint32_t dst = sb + stage * GM_STAGE + arr * GM_ARR
                               + r * GM_ROWB + cb * 16;
            const __nv_bfloat16* base =
                (arr == 0) ? Ahi : (arr == 1) ? Alo : (arr == 2) ? Bhi : Blo;
            const int grow = ((arr < 2) ? row0 : col0) + r;
            const void* src = base + (size_t)grow * KDIM + k0 + cb * 8;
            CP_ASYNC16(dst, src);
        }
    };

    prefetch(0, 0);
    CP_COMMIT();

    for (int c = 0; c < GM_NCH; c++) {
        if (c + 1 < GM_NCH) {
            prefetch((c + 1) & 1, c + 1);
            CP_COMMIT();
            CP_WAIT(1);
        } else {
            CP_WAIT(0);
        }
        __syncthreads();

        const uint32_t st = sb + (c & 1) * GM_STAGE;
        const uint32_t ahB = st;
        const uint32_t alB = st + GM_ARR;
        const uint32_t bhB = st + 2 * GM_ARR;
        const uint32_t blB = st + 3 * GM_ARR;

        #pragma unroll
        for (int ks = 0; ks < 2; ks++) {
            const int kcb = acb + 2 * ks;
            const int kbb = bcb + 2 * ks;
            uint32_t af[4][4], bh[2][4], bl[2][4];

            #pragma unroll
            for (int mt = 0; mt < 4; mt++)
                ldsm4(af[mt], ahB + (arow + mt * 16) * GM_ROWB + kcb * 16);
            #pragma unroll
            for (int p = 0; p < 2; p++)
                ldsm4(bh[p], bhB + (brow + p * 16) * GM_ROWB + kbb * 16);

            #pragma unroll
            for (int mt = 0; mt < 4; mt++)
                #pragma unroll
                for (int nt = 0; nt < 4; nt++)
                    mma16816(acc[mt * 4 + nt], af[mt], &bh[nt >> 1][(nt & 1) * 2]);

            #pragma unroll
            for (int p = 0; p < 2; p++)
                ldsm4(bl[p], blB + (brow + p * 16) * GM_ROWB + kbb * 16);

            #pragma unroll
            for (int mt = 0; mt < 4; mt++)
                #pragma unroll
                for (int nt = 0; nt < 4; nt++)
                    mma16816(acc[mt * 4 + nt], af[mt], &bl[nt >> 1][(nt & 1) * 2]);

            #pragma unroll
            for (int mt = 0; mt < 4; mt++)
                ldsm4(af[mt], alB + (arow + mt * 16) * GM_ROWB + kcb * 16);

            #pragma unroll
            for (int mt = 0; mt < 4; mt++)
                #pragma unroll
                for (int nt = 0; nt < 4; nt++)
                    mma16816(acc[mt * 4 + nt], af[mt], &bh[nt >> 1][(nt & 1) * 2]);
        }
        __syncthreads();
    }

    #pragma unroll
    for (int mt = 0; mt < 4; mt++) {
        const int row = row0 + warp_m * 64 + mt * 16 + (lane >> 2);
        #pragma unroll
        for (int nt = 0; nt < 4; nt++) {
            const int col = col0 + warp_n * 32 + nt * 8 + 2 * (lane & 3);
            const float b0 = bias[col], b1 = bias[col + 1];
            float* c = acc[mt * 4 + nt];
            float v0 = c[0] + b0, v1 = c[1] + b1;
            float v2 = c[2] + b0, v3 = c[3] + b1;
            if (!bf16out) {
                *(float2*)(C + (size_t)row * Ntot + col) = make_float2(v0, v1);
                *(float2*)(C + (size_t)(row + 8) * Ntot + col) = make_float2(v2, v3);
            } else {
                ushort2 h0, l0p, h1, l1p;
                split2(v0, h0.x, l0p.x); split2(v1, h0.y, l0p.y);
                split2(v2, h1.x, l1p.x); split2(v3, h1.y, l1p.y);
                size_t o0 = (size_t)row * Ntot + col;
                size_t o1 = (size_t)(row + 8) * Ntot + col;
                *(ushort2*)(Chi + o0) = h0; *(ushort2*)(Clo + o0) = l0p;
                *(ushort2*)(Chi + o1) = h1; *(ushort2*)(Clo + o1) = l1p;
            }
        }
    }
}

// ---------------------------------------------------------------------------
// HMMA flash attention, 128-key tiles, U aliased over B region.
// Per CTA: (b,h,qb) -> 64 queries. Per 128-key tile:
//   U = Q @ [K(128) ; ErBand(191)]^T  (M=64, N=320, K=64), hi/lo 3-pass
//   scores s[i][j] = (U[j] + U[255+i-j]) * scale ; mask j <= d0+i
//   online softmax (ex2.approx), P -> bf16 hi/lo (packed u32 stores)
//   O += P(64x128) @ V(128x64) via ldmatrix.trans, 3-pass
// ---------------------------------------------------------------------------
#define AT_RS 144
#define PS 272
#define US 324
#define O_QH 0
#define O_QL (O_QH + 64*AT_RS)
#define O_BH (O_QL + 64*AT_RS)
#define O_BL (O_BH + 320*AT_RS)
#define O_VH (O_BL + 320*AT_RS)
#define O_VL (O_VH + 128*AT_RS)
#define O_PH (O_VL + 128*AT_RS)
#define O_PL (O_PH + 64*PS)
#define O_U  O_BH                 // alias: U (82944B) over B region (92160B)
#define O_M  (O_PL + 64*PS)
#define O_L  (O_M + 256)
#define O_R  (O_L + 256)
#define AT_SMEM (O_R + 256)       // 183040 bytes

__global__ __launch_bounds__(256, 1) void attn_mma_kernel(
    const __nv_bfloat16* __restrict__ qkvh, const __nv_bfloat16* __restrict__ qkvl,
    const __nv_bfloat16* __restrict__ erh,  const __nv_bfloat16* __restrict__ erl,
    __nv_bfloat16* __restrict__ Yh, __nv_bfloat16* __restrict__ Yl)
{
    extern __shared__ char smem[];
    const uint32_t sb = smem_u32(smem);
    float* Usm = (float*)(smem + O_U);
    float* msm = (float*)(smem + O_M);
    float* lsm = (float*)(smem + O_L);
    float* rsc = (float*)(smem + O_R);

    const int tid = threadIdx.x;
    const int lane = tid & 31;
    const int wid = tid >> 5;
    const int warp_m = wid >> 2, warp_n = wid & 3;
    const int qb = blockIdx.x & 31;
    const int h  = (blockIdx.x >> 5) & 15;
    const int b  = blockIdx.x >> 9;
    const int l0 = qb * 64;
    const size_t rowbase = (size_t)(b * LSEQ);

    // Q tile hi/lo -> smem
    #pragma unroll
    for (int it = 0; it < 4; it++) {
        int id = tid + it * 256;
        int arr = id >> 9, rem = id & 511;
        int r = rem >> 3, u = rem & 7;
        const __nv_bfloat16* s = (arr ? qkvl : qkvh)
            + (rowbase + l0 + r) * 3072 + h * HSZ + u * 8;
        CP_ASYNC16(sb + (arr ? O_QL : O_QH) + r * AT_RS + u * 16, s);
    }
    CP_COMMIT();
    if (tid < 64) { msm[tid] = -1e30f; lsm[tid] = 0.f; }

    float O[2][2][4];
    #pragma unroll
    for (int a = 0; a < 2; a++)
        #pragma unroll
        for (int c = 0; c < 2; c++)
            #pragma unroll
            for (int q = 0; q < 4; q++) O[a][c][q] = 0.f;

    const int arow = warp_m * 32 + (lane & 15);
    const int acb  = lane >> 4;
    const int brow = warp_n * 80 + ((lane >> 4) & 1) * 8 + (lane & 7);
    const int bcb  = (lane >> 3) & 1;
    const int vrow = lane & 15;
    const int vcolB = warp_n * 32 + (lane >> 4) * 16;   // byte offset in V row

    const float sc2 = 0.125f * 1.4426950408889634f;
    const int ntiles = (qb >> 1) + 1;

    for (int kb2 = 0; kb2 < ntiles; kb2++) {
        const int m0 = kb2 * 128;
        const int d0 = l0 - m0;
        __syncthreads();   // previous tile's smem fully consumed

        // ---- loads: K(128 rows), V(128 rows), ErBand(191 rows), hi+lo ----
        #pragma unroll
        for (int it = 0; it < 8; it++) {       // K: 2048 chunks
            int id = tid + it * 256;
            int arr = id >> 10, rem = id & 1023;
            int r = rem >> 3, u = rem & 7;
            const __nv_bfloat16* s = (arr ? qkvl : qkvh)
                + (rowbase + m0 + r) * 3072 + DMODEL + h * HSZ + u * 8;
            CP_ASYNC16(sb + (arr ? O_BL : O_BH) + r * AT_RS + u * 16, s);
        }
        #pragma unroll
        for (int it = 0; it < 8; it++) {       // V: 2048 chunks
            int id = tid + it * 256;
            int arr = id >> 10, rem = id & 1023;
            int r = rem >> 3, u = rem & 7;
            const __nv_bfloat16* s = (arr ? qkvl : qkvh)
                + (rowbase + m0 + r) * 3072 + 2 * DMODEL + h * HSZ + u * 8;
            CP_ASYNC16(sb + (arr ? O_VL : O_VH) + r * AT_RS + u * 16, s);
        }
        #pragma unroll
        for (int it = 0; it < 12; it++) {      // Er: 2x192x8 = 3072 slots (191 used)
            int id = tid + it * 256;
            int q = id >> 3, u = id & 7;
            int arr = (q >= 192);
            int t = arr ? q - 192 : q;
            int g = (LSEQ + 126 - d0) - t;
            bool ok = (t < 191) && (g >= 0) && (g < LSEQ);
            const __nv_bfloat16* s = (arr ? erl : erh)
                + (ok ? (size_t)g * HSZ : 0) + u * 8;
            cp16z(sb + (arr ? O_BL : O_BH) + (128 + t) * AT_RS + u * 16, s, ok);
        }
        CP_COMMIT();
        CP_WAIT(0);
        __syncthreads();

        // ---- U = Q @ [K;ErB]^T : M=64, N=320, 3-pass hi/lo ----
        {
            float u[20][4];
            #pragma unroll
            for (int i = 0; i < 20; i++)
                #pragma unroll
                for (int q = 0; q < 4; q++) u[i][q] = 0.f;

            #pragma unroll
            for (int ks = 0; ks < 4; ks++) {
                uint32_t af[2][4], bhf[5][4], blf[5][4];
                #pragma unroll
                for (int mt = 0; mt < 2; mt++)
                    ldsm4(af[mt], sb + O_QH + (arow + mt * 16) * AT_RS + (acb + 2 * ks) * 16);
                #pragma unroll
                for (int p = 0; p < 5; p++)
                    ldsm4(bhf[p], sb + O_BH + (brow + p * 16) * AT_RS + (bcb + 2 * ks) * 16);
                #pragma unroll
                for (int mt = 0; mt < 2; mt++)
                    #pragma unroll
                    for (int nt = 0; nt < 10; nt++)
                        mma16816(u[mt * 10 + nt], af[mt], &bhf[nt >> 1][(nt & 1) * 2]);
                #pragma unroll
                for (int p = 0; p < 5; p++)
                    ldsm4(blf[p], sb + O_BL + (brow + p * 16) * AT_RS + (bcb + 2 * ks) * 16);
                #pragma unroll
                for (int mt = 0; mt < 2; mt++)
                    #pragma unroll
                    for (int nt = 0; nt < 10; nt++)
                        mma16816(u[mt * 10 + nt], af[mt], &blf[nt >> 1][(nt & 1) * 2]);
                #pragma unroll
                for (int mt = 0; mt < 2; mt++)
                    ldsm4(af[mt], sb + O_QL + (arow + mt * 16) * AT_RS + (acb + 2 * ks) * 16);
                #pragma unroll
                for (int mt = 0; mt < 2; mt++)
                    #pragma unroll
                    for (int nt = 0; nt < 10; nt++)
                        mma16816(u[mt * 10 + nt], af[mt], &bhf[nt >> 1][(nt & 1) * 2]);
            }
            __syncthreads();   // all ldsm reads of B done before U overwrites it
            #pragma unroll
            for (int mt = 0; mt < 2; mt++) {
                int row = warp_m * 32 + mt * 16 + (lane >> 2);
                #pragma unroll
                for (int nt = 0; nt < 10; nt++) {
                    int col = warp_n * 80 + nt * 8 + 2 * (lane & 3);
                    float* up = &Usm[row * US + col];
                    *(float2*)up = make_float2(u[mt * 10 + nt][0], u[mt * 10 + nt][1]);
                    *(float2*)(up + 8 * US) = make_float2(u[mt * 10 + nt][2], u[mt * 10 + nt][3]);
                }
            }
        }
        __syncthreads();

        // ---- online softmax over 128 keys; write P hi/lo (packed) ----
        {
            const int r = tid >> 2, sub = tid & 3;
            const float mold = msm[r];
            const float* ur = &Usm[r * US];
            float sv[32], mx = -1e30f;
            #pragma unroll
            for (int n = 0; n < 32; n++) {
                int j = sub * 32 + n;
                float s = (ur[j] + ur[255 + r - j]) * sc2;
                bool valid = (j <= d0 + r);
                s = valid ? s : -1e30f;
                sv[n] = s;
                mx = fmaxf(mx, s);
            }
            mx = fmaxf(mx, __shfl_xor_sync(0xffffffffu, mx, 1));
            mx = fmaxf(mx, __shfl_xor_sync(0xffffffffu, mx, 2));
            const float mnew = fmaxf(mold, mx);
            float ps = 0.f;
            #pragma unroll
            for (int n = 0; n < 32; n += 2) {
                int j = sub * 32 + n;
                float p0 = ex2(sv[n] - mnew);
                float p1 = ex2(sv[n + 1] - mnew);
                ps += p0 + p1;
                unsigned short h0, l0b, h1, l1b;
                split2(p0, h0, l0b);
                split2(p1, h1, l1b);
                *(uint32_t*)(smem + O_PH + r * PS + 2 * j) =
                    (uint32_t)h0 | ((uint32_t)h1 << 16);
                *(uint32_t*)(smem + O_PL + r * PS + 2 * j) =
                    (uint32_t)l0b | ((uint32_t)l1b << 16);
            }
            ps += __shfl_xor_sync(0xffffffffu, ps, 1);
            ps += __shfl_xor_sync(0xffffffffu, ps, 2);
            if (sub == 0) {
                float sc = ex2(mold - mnew);
                rsc[r] = sc;
                msm[r] = mnew;
                lsm[r] = lsm[r] * sc + ps;
            }
        }
        __syncthreads();

        // ---- O rescale + PV (P 64x128 @ V 128x64, 3-pass) ----
        {
            #pragma unroll
            for (int mt = 0; mt < 2; mt++) {
                int row = warp_m * 32 + mt * 16 + (lane >> 2);
                float rs0 = rsc[row], rs1 = rsc[row + 8];
                #pragma unroll
                for (int nt = 0; nt < 2; nt++) {
                    O[mt][nt][0] *= rs0; O[mt][nt][1] *= rs0;
                    O[mt][nt][2] *= rs1; O[mt][nt][3] *= rs1;
                }
            }
            #pragma unroll
            for (int ks = 0; ks < 8; ks++) {
                uint32_t pf[2][4], vhf[4], vlf[4];
                #pragma unroll
                for (int mt = 0; mt < 2; mt++)
                    ldsm4(pf[mt], sb + O_PH + (arow + mt * 16) * PS + (acb + 2 * ks) * 16);
                ldsm4t(vhf, sb + O_VH + (ks * 16 + vrow) * AT_RS + vcolB);
                #pragma unroll
                for (int mt = 0; mt < 2; mt++)
                    #pragma unroll
                    for (int nt = 0; nt < 2; nt++)
                        mma16816(O[mt][nt], pf[mt], &vhf[nt * 2]);
                ldsm4t(vlf, sb + O_VL + (ks * 16 + vrow) * AT_RS + vcolB);
                #pragma unroll
                for (int mt = 0; mt < 2; mt++)
                    #pragma unroll
                    for (int nt = 0; nt < 2; nt++)
                        mma16816(O[mt][nt], pf[mt], &vlf[nt * 2]);
                #pragma unroll
                for (int mt = 0; mt < 2; mt++)
                    ldsm4(pf[mt], sb + O_PL + (arow + mt * 16) * PS + (acb + 2 * ks) * 16);
                #pragma unroll
                for (int mt = 0; mt < 2; mt++)
                    #pragma unroll
                    for (int nt = 0; nt < 2; nt++)
                        mma16816(O[mt][nt], pf[mt], &vhf[nt * 2]);
            }
        }
    }

    // ---- normalize + write y hi/lo ----
    #pragma unroll
    for (int mt = 0; mt < 2; mt++) {
        int row = warp_m * 32 + mt * 16 + (lane >> 2);
        #pragma unroll
        for (int half = 0; half < 2; half++) {
            int rr = row + half * 8;
            float inv = 1.0f / lsm[rr];
            #pragma unroll
            for (int nt = 0; nt < 2; nt++) {
                int d = warp_n * 16 + nt * 8 + 2 * (lane & 3);
                float v0 = O[mt][nt][half * 2 + 0] * inv;
                float v1 = O[mt][nt][half * 2 + 1] * inv;
                ushort2 hv, lv;
                split2(v0, hv.x, lv.x);
                split2(v1, hv.y, lv.y);
                size_t off = (rowbase + l0 + rr) * DMODEL + h * HSZ + d;
                *(ushort2*)(Yh + off) = hv;
                *(ushort2*)(Yl + off) = lv;
            }
        }
    }
}

// ---------------------------------------------------------------------------
// kernel_launch
// Inputs (metadata order): x, W_attn, b_attn, Er, W_proj, b_proj
// ---------------------------------------------------------------------------
extern "C" void kernel_launch(void* const* d_in, const int* in_sizes, int n_in,
                              void* d_out, int out_size)
{
    const float* x      = (const float*)d_in[0];
    const float* W_attn = (const float*)d_in[1];
    const float* b_attn = (const float*)d_in[2];
    const float* Er     = (const float*)d_in[3];
    const float* W_proj = (const float*)d_in[4];
    const float* b_proj = (const float*)d_in[5];
    float* out = (float*)d_out;

    void *p_xhi, *p_xlo, *p_wthi, *p_wtlo, *p_qh, *p_ql, *p_eh, *p_el, *p_yh, *p_yl;
    cudaGetSymbolAddress(&p_xhi, g_xhi);
    cudaGetSymbolAddress(&p_xlo, g_xlo);
    cudaGetSymbolAddress(&p_wthi, g_wthi);
    cudaGetSymbolAddress(&p_wtlo, g_wtlo);
    cudaGetSymbolAddress(&p_qh, g_qkvhi);
    cudaGetSymbolAddress(&p_ql, g_qkvlo);
    cudaGetSymbolAddress(&p_eh, g_erhi);
    cudaGetSymbolAddress(&p_el, g_erlo);
    cudaGetSymbolAddress(&p_yh, g_yhi);
    cudaGetSymbolAddress(&p_yl, g_ylo);
    __nv_bfloat16* xhi = (__nv_bfloat16*)p_xhi;
    __nv_bfloat16* xlo = (__nv_bfloat16*)p_xlo;
    __nv_bfloat16* wthi = (__nv_bfloat16*)p_wthi;
    __nv_bfloat16* wtlo = (__nv_bfloat16*)p_wtlo;
    __nv_bfloat16* qh = (__nv_bfloat16*)p_qh;
    __nv_bfloat16* ql = (__nv_bfloat16*)p_ql;
    __nv_bfloat16* eh = (__nv_bfloat16*)p_eh;
    __nv_bfloat16* el = (__nv_bfloat16*)p_el;
    __nv_bfloat16* yh = (__nv_bfloat16*)p_yh;
    __nv_bfloat16* yl = (__nv_bfloat16*)p_yl;

    cudaFuncSetAttribute(gemm_mma_kernel,
                         cudaFuncAttributeMaxDynamicSharedMemorySize, GM_SMEM);
    cudaFuncSetAttribute(attn_mma_kernel,
                         cudaFuncAttributeMaxDynamicSharedMemorySize, AT_SMEM);

    // 1) weight/input prep
    transpose_split_kernel<<<dim3(3 * DMODEL / 32, KDIM / 32), dim3(32, 8)>>>(
        W_attn, wthi, wtlo, KDIM, 3 * DMODEL);
    split_bf16_kernel<<<(MTOT * KDIM) / 1024, 256>>>(x, xhi, xlo, MTOT * KDIM);
    split_bf16_kernel<<<(LSEQ * HSZ) / 1024, 256>>>(Er, eh, el, LSEQ * HSZ);

    // 2) qkv = x @ W_attn + b_attn -> bf16 hi/lo
    gemm_mma_kernel<<<dim3(3 * DMODEL / 128, MTOT / 128), 256, GM_SMEM>>>(
        xhi, xlo, wthi, wtlo, b_attn, nullptr, 3 * DMODEL, qh, ql, 1);

    // 3) attention -> y bf16 hi/lo
    attn_mma_kernel<<<BATCH * NHEAD * (LSEQ / 64), 256, AT_SMEM>>>(
        qh, ql, eh, el, yh, yl);

    // 4) proj
    transpose_split_kernel<<<dim3(DMODEL / 32, KDIM / 32), dim3(32, 8)>>>(
        W_proj, wthi, wtlo, KDIM, DMODEL);
    gemm_mma_kernel<<<dim3(DMODEL / 128, MTOT / 128), 256, GM_SMEM>>>(
        yh, yl, wthi, wtlo, b_proj, out, DMODEL, nullptr, nullptr, 0);
}